// round 11
// baseline (speedup 1.0000x reference)
#include <cuda_runtime.h>
#include <cstdint>

// ---------------------------------------------------------------------------
// MPEdgeNodeBlock — TF32 mma.sync.  R11: each 4-layer MLP fused into ONE
// kernel: activations stay in smem (64-row tiles, ping/pong), weights
// streamed via double-buffered cp.async.  Kills ~1.8GB of inter-layer DRAM
// round-trips and 12 launches.
// ---------------------------------------------------------------------------
#define N_NODES  25000
#define NODE_PAD 25024            // 391 * 64 pad, cp.async never OOB
#define N_EDGES  200000
#define IN_F     64
#define OUT_F    64
#define HDIM     192

// -------------------- scratch (device globals; no runtime alloc) ------------
__device__ __align__(16) float g_Xr[NODE_PAD * HDIM];
__device__ __align__(16) float g_Xi[NODE_PAD * HDIM];
__device__ __align__(16) float g_Er[(size_t)N_EDGES * OUT_F];
__device__ __align__(16) float g_Ei[(size_t)N_EDGES * OUT_F];
__device__ int g_row[N_EDGES];
__device__ int g_col[N_EDGES];
__device__ int g_is64;
// tf32-pre-rounded weights, concatenated
#define W_TOTAL 253952
__device__ __align__(16) float g_Wt[W_TOTAL];
#define OFF_WN   0
#define OFF_WE   4096
#define OFF_NW   8192
#define OFF_NOW  118784
#define OFF_EW   131072
#define OFF_EOW  241664

// -------------------- helpers ------------------------------------------------
__device__ __forceinline__ uint32_t smem_u32(const void* p) {
    uint32_t a;
    asm("{ .reg .u64 t; cvta.to.shared.u64 t, %1; cvt.u32.u64 %0, t; }"
        : "=r"(a) : "l"(p));
    return a;
}

__device__ __forceinline__ float tf32r(float f) {
    uint32_t r;
    asm("cvt.rna.tf32.f32 %0, %1;" : "=r"(r) : "f"(f));
    return __uint_as_float(r);
}

__device__ __forceinline__ void ldsm_x4(uint32_t& r0, uint32_t& r1,
                                        uint32_t& r2, uint32_t& r3,
                                        uint32_t addr) {
    asm volatile("ldmatrix.sync.aligned.m8n8.x4.shared.b16 {%0,%1,%2,%3}, [%4];"
                 : "=r"(r0), "=r"(r1), "=r"(r2), "=r"(r3) : "r"(addr));
}

__device__ __forceinline__ void mma_tf32(float* c, const uint32_t* a,
                                         const uint32_t* b) {
    asm volatile(
        "mma.sync.aligned.m16n8k8.row.col.f32.tf32.tf32.f32 "
        "{%0,%1,%2,%3}, {%4,%5,%6,%7}, {%8,%9}, {%0,%1,%2,%3};"
        : "+f"(c[0]), "+f"(c[1]), "+f"(c[2]), "+f"(c[3])
        : "r"(a[0]), "r"(a[1]), "r"(a[2]), "r"(a[3]), "r"(b[0]), "r"(b[1]));
}

__device__ __forceinline__ void cp16(uint32_t dst, const void* src) {
    asm volatile("cp.async.cg.shared.global [%0], [%1], 16;"
                 :: "r"(dst), "l"(src));
}

// -------------------- edge_index dtype detection + conversion ---------------
__global__ void k_detect(const unsigned int* __restrict__ p) {
    if (threadIdx.x == 0) {
        int all_zero = 1;
        for (int i = 0; i < 128; ++i)
            if (p[2 * i + 1] != 0u) { all_zero = 0; break; }
        g_is64 = all_zero;
    }
}

__global__ void k_convert(const void* __restrict__ raw) {
    int e = blockIdx.x * blockDim.x + threadIdx.x;
    if (e >= N_EDGES) return;
    if (g_is64) {
        const long long* p = (const long long*)raw;
        g_row[e] = (int)p[2 * e];
        g_col[e] = (int)p[2 * e + 1];
    } else {
        const int* p = (const int*)raw;
        g_row[e] = p[2 * e];
        g_col[e] = p[2 * e + 1];
    }
}

// -------------------- weight prep: round to tf32 once ------------------------
__global__ void k_prepW(const float* s0, const float* s1, const float* s2,
                        const float* s3, const float* s4, const float* s5) {
    const int sizes[6] = {4096, 4096, 110592, 12288, 110592, 12288};
    const int offs[6]  = {OFF_WN, OFF_WE, OFF_NW, OFF_NOW, OFF_EW, OFF_EOW};
    int t = blockIdx.y;
    const float* s = (t == 0) ? s0 : (t == 1) ? s1 : (t == 2) ? s2
                   : (t == 3) ? s3 : (t == 4) ? s4 : s5;
    for (int i = blockIdx.x * blockDim.x + threadIdx.x; i < sizes[t];
         i += gridDim.x * blockDim.x)
        g_Wt[offs[t] + i] = tf32r(s[i]);
}

__global__ void k_zeroX() {
    int i = blockIdx.x * blockDim.x + threadIdx.x;
    if (i < N_NODES * HDIM) { g_Xr[i] = 0.f; g_Xi[i] = 0.f; }
}

__global__ void k_roundX() {
    int i = blockIdx.x * blockDim.x + threadIdx.x;
    if (i < N_NODES * HDIM) {
        g_Xr[i] = tf32r(g_Xr[i]);
        g_Xi[i] = tf32r(g_Xi[i]);
    }
}

// -------------------- projection GEMM (K=64): C = A @ W^T + b ---------------
__global__ __launch_bounds__(256)
void k_proj(const float* __restrict__ A, int M,
            const float* __restrict__ W,
            const float* __restrict__ bias,
            float* __restrict__ C, int ldc)
{
    constexpr int K = 64, KPAD = 68, vpr = 16;
    extern __shared__ __align__(16) char smem[];
    float* As = reinterpret_cast<float*>(smem);
    float* Bs = As + 64 * KPAD;
    const uint32_t As32 = smem_u32(As);
    const uint32_t Bs32 = smem_u32(Bs);

    const int tid = threadIdx.x, lane = tid & 31, wid = tid >> 5;
    const int wm = wid >> 2, wn = wid & 3;
    const int bm = blockIdx.x * 64;

    for (int idx = tid; idx < 64 * vpr; idx += 256) {
        int row = idx / vpr, c4 = (idx - row * vpr) * 4, gm = bm + row;
        float4 v = make_float4(0.f, 0.f, 0.f, 0.f);
        if (gm < M)
            v = *reinterpret_cast<const float4*>(A + (size_t)gm * K + c4);
        *reinterpret_cast<float4*>(As + row * KPAD + c4) =
            make_float4(tf32r(v.x), tf32r(v.y), tf32r(v.z), tf32r(v.w));
    }
    for (int idx = tid; idx < 64 * vpr; idx += 256) {
        int n = idx / vpr, c4 = (idx - n * vpr) * 4;
        cp16(Bs32 + (uint32_t)((n * KPAD + c4) * 4), W + (size_t)n * K + c4);
    }
    asm volatile("cp.async.commit_group;");
    asm volatile("cp.async.wait_group 0;");
    __syncthreads();

    const uint32_t aAddr = As32 +
        (uint32_t)(((wm * 32 + (lane & 15)) * KPAD + (lane >> 4) * 4) * 4);
    const int nOff = (lane & 7) + ((lane >> 4) & 1) * 8;
    const uint32_t bAddr = Bs32 +
        (uint32_t)(((wn * 16 + nOff) * KPAD + ((lane >> 3) & 1) * 4) * 4);

    float c[2][2][4];
#pragma unroll
    for (int i = 0; i < 2; ++i)
#pragma unroll
        for (int j = 0; j < 2; ++j)
#pragma unroll
            for (int q = 0; q < 4; ++q) c[i][j][q] = 0.f;

#pragma unroll
    for (int ks = 0; ks < K / 8; ++ks) {
        const uint32_t kb = (uint32_t)(ks * 32);
        uint32_t a0[4], a1[4], b[4];
        ldsm_x4(a0[0], a0[1], a0[2], a0[3], aAddr + kb);
        ldsm_x4(a1[0], a1[1], a1[2], a1[3], aAddr + (uint32_t)(16 * KPAD * 4) + kb);
        ldsm_x4(b[0], b[1], b[2], b[3], bAddr + kb);
        mma_tf32(c[0][0], a0, b);
        mma_tf32(c[0][1], a0, b + 2);
        mma_tf32(c[1][0], a1, b);
        mma_tf32(c[1][1], a1, b + 2);
    }

#pragma unroll
    for (int nt = 0; nt < 2; ++nt) {
        int col = wn * 16 + nt * 8 + (lane & 3) * 2;
        float bx = __ldg(bias + col);
        float by = __ldg(bias + col + 1);
#pragma unroll
        for (int mt = 0; mt < 2; ++mt) {
            int row0 = bm + wm * 32 + mt * 16 + (lane >> 2);
            float v0 = tf32r(c[mt][nt][0] + bx);
            float v1 = tf32r(c[mt][nt][1] + by);
            float v2 = tf32r(c[mt][nt][2] + bx);
            float v3 = tf32r(c[mt][nt][3] + by);
            if (row0 < M)
                *reinterpret_cast<float2*>(C + (size_t)row0 * ldc + col) =
                    make_float2(v0, v1);
            if (row0 + 8 < M)
                *reinterpret_cast<float2*>(C + (size_t)(row0 + 8) * ldc + col) =
                    make_float2(v2, v3);
        }
    }
}

// -------------------- fused 4-layer MLP -------------------------------------
// MODE 0 (node): A = g_X* (pre-rounded, 192-wide, cp.async).
// MODE 1 (edge): A tile = concat(E[e,0:64], H[row[e]], H[col[e]]), cvt staged.
// Block = 64 rows through all 4 layers; acts in smem ping/pong; W chunks
// (64n x 192k) double-buffered via cp.async.  10 chunks: 3+3+3+1.
template <int MODE>
__global__ __launch_bounds__(256)
void k_mlp(const float* __restrict__ A, int M,
           const float* __restrict__ Wm,     // 3 * 192*192 (tf32)
           const float* __restrict__ Wo,     // 64 * 192 (tf32)
           const float* __restrict__ bs,     // 3 * 192
           const float* __restrict__ alphas, // 3
           const float* __restrict__ bo,     // 64
           float* __restrict__ Cout,         // M x 64
           const float* __restrict__ GH)     // gather source (edge mode)
{
    constexpr int K = 192, KPAD = 196, vpr = 48;
    constexpr int HHc = 192 * 192;
    extern __shared__ __align__(16) char smem[];
    float* bufA = reinterpret_cast<float*>(smem);
    float* bufB = bufA + 64 * KPAD;
    float* wbuf[2] = { bufB + 64 * KPAD, bufB + 128 * KPAD };

    const int tid = threadIdx.x, lane = tid & 31, wid = tid >> 5;
    const int wm = wid >> 2, wn = wid & 3;
    const int bm = blockIdx.x * 64;

    // ---- stage input tile into bufA ----
    if (MODE == 0) {
        for (int idx = tid; idx < 64 * vpr; idx += 256) {
            int row = idx / vpr, c4 = (idx - row * vpr) * 4;
            cp16(smem_u32(bufA + row * KPAD + c4),
                 A + (size_t)(bm + row) * K + c4);
        }
        asm volatile("cp.async.commit_group;");
    } else {
        for (int idx = tid; idx < 64 * vpr; idx += 256) {
            int row = idx / vpr, c4 = (idx - row * vpr) * 4, e = bm + row;
            int seg = c4 >> 6, off = c4 & 63;
            const float* src;
            if (seg == 0) {
                src = A + (size_t)e * 64 + off;
            } else {
                int n = (seg == 1) ? __ldg(&g_row[e]) : __ldg(&g_col[e]);
                src = GH + (size_t)n * 64 + off;
            }
            float4 v = *reinterpret_cast<const float4*>(src);
            *reinterpret_cast<float4*>(bufA + row * KPAD + c4) =
                make_float4(tf32r(v.x), tf32r(v.y), tf32r(v.z), tf32r(v.w));
        }
    }

    // ---- issue W chunk 0 ----
    {
        float* dst = wbuf[0];
        for (int idx = tid; idx < 64 * vpr; idx += 256) {
            int n = idx / vpr, c4 = (idx - n * vpr) * 4;
            cp16(smem_u32(dst + n * KPAD + c4), Wm + (size_t)n * K + c4);
        }
        asm volatile("cp.async.commit_group;");
    }

    float* cur = bufA;
    float* nxt = bufB;
    const int nOff = (lane & 7) + ((lane >> 4) & 1) * 8;
    const int aLane = (wm * 32 + (lane & 15)) * KPAD + (lane >> 4) * 4;
    const int bLane = nOff * KPAD + ((lane >> 3) & 1) * 4;

    for (int i = 0; i < 10; ++i) {
        const int l  = (i < 9) ? (i / 3) : 3;
        const int nb = (i < 9) ? (i % 3) * 64 : 0;

        // prefetch next W chunk into other slot, then wait for current
        if (i + 1 < 10) {
            const float* wn_ = (i + 1 < 9)
                ? (Wm + (size_t)((i + 1) / 3) * HHc + (size_t)((i + 1) % 3) * 64 * K)
                : Wo;
            float* dst = wbuf[(i + 1) & 1];
            for (int idx = tid; idx < 64 * vpr; idx += 256) {
                int n = idx / vpr, c4 = (idx - n * vpr) * 4;
                cp16(smem_u32(dst + n * KPAD + c4), wn_ + (size_t)n * K + c4);
            }
            asm volatile("cp.async.commit_group;");
            asm volatile("cp.async.wait_group 1;");
        } else {
            asm volatile("cp.async.wait_group 0;");
        }
        __syncthreads();

        const uint32_t aAddr = smem_u32(cur) + (uint32_t)(aLane * 4);
        const uint32_t bAddr = smem_u32(wbuf[i & 1]) +
                               (uint32_t)((wn * 16 * KPAD + bLane) * 4);

        float c[2][2][4];
#pragma unroll
        for (int x = 0; x < 2; ++x)
#pragma unroll
            for (int y = 0; y < 2; ++y)
#pragma unroll
                for (int q = 0; q < 4; ++q) c[x][y][q] = 0.f;

#pragma unroll
        for (int ks = 0; ks < 24; ++ks) {
            const uint32_t kb = (uint32_t)(ks * 32);
            uint32_t a0[4], a1[4], b[4];
            ldsm_x4(a0[0], a0[1], a0[2], a0[3], aAddr + kb);
            ldsm_x4(a1[0], a1[1], a1[2], a1[3], aAddr + (uint32_t)(16 * KPAD * 4) + kb);
            ldsm_x4(b[0], b[1], b[2], b[3], bAddr + kb);
            mma_tf32(c[0][0], a0, b);
            mma_tf32(c[0][1], a0, b + 2);
            mma_tf32(c[1][0], a1, b);
            mma_tf32(c[1][1], a1, b + 2);
        }

        // ---- epilogue ----
        const bool  act = (l < 3);
        const float al  = act ? __ldg(alphas + l) : 1.0f;
        const float* bias = act ? (bs + l * 192 + nb) : bo;

#pragma unroll
        for (int nt = 0; nt < 2; ++nt) {
            int col = wn * 16 + nt * 8 + (lane & 3) * 2;     // 0..63 chunk-local
            float bx = __ldg(bias + col);
            float by = __ldg(bias + col + 1);
#pragma unroll
            for (int mt = 0; mt < 2; ++mt) {
                int row0 = wm * 32 + mt * 16 + (lane >> 2);  // block-local
                float v0 = c[mt][nt][0] + bx;
                float v1 = c[mt][nt][1] + by;
                float v2 = c[mt][nt][2] + bx;
                float v3 = c[mt][nt][3] + by;
                if (act) {
                    v0 = (v0 >= 0.f) ? v0 : al * v0;
                    v1 = (v1 >= 0.f) ? v1 : al * v1;
                    v2 = (v2 >= 0.f) ? v2 : al * v2;
                    v3 = (v3 >= 0.f) ? v3 : al * v3;
                    // intermediate: round to tf32, keep in smem
                    *reinterpret_cast<float2*>(nxt + row0 * KPAD + nb + col) =
                        make_float2(tf32r(v0), tf32r(v1));
                    *reinterpret_cast<float2*>(nxt + (row0 + 8) * KPAD + nb + col) =
                        make_float2(tf32r(v2), tf32r(v3));
                } else {
                    int gm = bm + row0;
                    if (gm < M)
                        *reinterpret_cast<float2*>(Cout + (size_t)gm * 64 + col) =
                            make_float2(v0, v1);
                    if (gm + 8 < M)
                        *reinterpret_cast<float2*>(Cout + (size_t)(gm + 8) * 64 + col) =
                            make_float2(v2, v3);
                }
            }
        }
        __syncthreads();
        if (i == 2 || i == 5 || i == 8) { float* t = cur; cur = nxt; nxt = t; }
    }
}

// -------------------- node aggregation (segment-sum via atomics) ------------
__global__ void k_scatter() {
    int t = blockIdx.x * blockDim.x + threadIdx.x;
    if (t >= N_EDGES * IN_F) return;
    int e = t >> 6;
    int f = t & 63;
    int r = g_row[e];
    int c = g_col[e];

    float vnr = g_Xr[(size_t)c * HDIM + f];
    float vni = g_Xi[(size_t)c * HDIM + f];
    float ver = g_Er[(size_t)e * 64 + f];
    float vei = g_Ei[(size_t)e * 64 + f];

    atomicAdd(&g_Xr[(size_t)r * HDIM + 64  + f], vnr);
    atomicAdd(&g_Xr[(size_t)r * HDIM + 128 + f], ver);
    atomicAdd(&g_Xi[(size_t)r * HDIM + 64  + f], vni);
    atomicAdd(&g_Xi[(size_t)r * HDIM + 128 + f], vei);
}

// ---------------------------------------------------------------------------
static float* symaddr(const void* sym) {
    void* p = nullptr;
    cudaGetSymbolAddress(&p, sym);
    return (float*)p;
}

extern "C" void kernel_launch(void* const* d_in, const int* in_sizes, int n_in,
                              void* d_out, int out_size)
{
    const float* node_real = (const float*)d_in[0];
    const float* node_imag = (const float*)d_in[1];
    const float* edge_real = (const float*)d_in[2];
    const float* edge_imag = (const float*)d_in[3];
    const void*  edge_idx  = d_in[4];
    const float* Wn        = (const float*)d_in[5];
    const float* bn_       = (const float*)d_in[6];
    const float* We        = (const float*)d_in[7];
    const float* be_       = (const float*)d_in[8];
    const float* node_W    = (const float*)d_in[9];
    const float* node_b    = (const float*)d_in[10];
    const float* node_al   = (const float*)d_in[11];
    const float* node_oW   = (const float*)d_in[12];
    const float* node_ob   = (const float*)d_in[13];
    const float* edge_W    = (const float*)d_in[14];
    const float* edge_b    = (const float*)d_in[15];
    const float* edge_al   = (const float*)d_in[16];
    const float* edge_oW   = (const float*)d_in[17];
    const float* edge_ob   = (const float*)d_in[18];

    float* out  = (float*)d_out;
    float* hr   = out;
    float* hi   = out + (size_t)N_NODES * OUT_F;
    float* outr = out + 2 * (size_t)N_NODES * OUT_F;
    float* outi = outr + (size_t)N_EDGES * OUT_F;

    float* Xr = symaddr(g_Xr);
    float* Xi = symaddr(g_Xi);
    float* Er = symaddr(g_Er);
    float* Ei = symaddr(g_Ei);
    float* Wt = symaddr(g_Wt);

    const int SMEM_PROJ = 128 * 68 * 4;          // 34.8 KB
    const int SMEM_MLP  = 4 * 64 * 196 * 4;      // 200.7 KB
    cudaFuncSetAttribute(k_proj,    cudaFuncAttributeMaxDynamicSharedMemorySize, SMEM_PROJ);
    cudaFuncSetAttribute(k_mlp<0>,  cudaFuncAttributeMaxDynamicSharedMemorySize, SMEM_MLP);
    cudaFuncSetAttribute(k_mlp<1>,  cudaFuncAttributeMaxDynamicSharedMemorySize, SMEM_MLP);

    const int TPB = 256;
    const int gN  = (N_NODES + 63) / 64;   // 391
    const int gE  = N_EDGES / 64;          // 3125
    const int HH  = HDIM * HDIM;

    // 1-2. edge index conversion
    k_detect<<<1, 32>>>((const unsigned int*)edge_idx);
    k_convert<<<(N_EDGES + TPB - 1) / TPB, TPB>>>(edge_idx);

    // 3. weight prep (tf32 round)
    k_prepW<<<dim3(432, 6), TPB>>>(Wn, We, node_W, node_oW, edge_W, edge_oW);

    // 4. zero node agg buffers
    k_zeroX<<<(N_NODES * HDIM + TPB - 1) / TPB, TPB>>>();

    // 5-8. projections
    k_proj<<<gE, TPB, SMEM_PROJ>>>(edge_real, N_EDGES, Wt + OFF_WE, be_, Er, OUT_F);
    k_proj<<<gE, TPB, SMEM_PROJ>>>(edge_imag, N_EDGES, Wt + OFF_WE, be_, Ei, OUT_F);
    k_proj<<<gN, TPB, SMEM_PROJ>>>(node_real, N_NODES, Wt + OFF_WN, bn_, Xr, HDIM);
    k_proj<<<gN, TPB, SMEM_PROJ>>>(node_imag, N_NODES, Wt + OFF_WN, bn_, Xi, HDIM);

    // 9-10. node aggregation + tf32 round
    k_scatter<<<(N_EDGES * IN_F + TPB - 1) / TPB, TPB>>>();
    k_roundX<<<(N_NODES * HDIM + TPB - 1) / TPB, TPB>>>();

    // 11-12. node MLPs (fused 4 layers) -> hr / hi
    k_mlp<0><<<gN, TPB, SMEM_MLP>>>(Xr, N_NODES, Wt + OFF_NW, Wt + OFF_NOW,
                                    node_b, node_al, node_ob, hr, nullptr);
    k_mlp<0><<<gN, TPB, SMEM_MLP>>>(Xi, N_NODES, Wt + OFF_NW, Wt + OFF_NOW,
                                    node_b, node_al, node_ob, hi, nullptr);

    // 13-14. edge MLPs (fused gather + 4 layers) -> outr / outi
    k_mlp<1><<<gE, TPB, SMEM_MLP>>>(Er, N_EDGES, Wt + OFF_EW, Wt + OFF_EOW,
                                    edge_b, edge_al, edge_ob, outr, hr);
    k_mlp<1><<<gE, TPB, SMEM_MLP>>>(Ei, N_EDGES, Wt + OFF_EW, Wt + OFF_EOW,
                                    edge_b, edge_al, edge_ob, outi, hi);
}

// round 13
// speedup vs baseline: 1.1022x; 1.1022x over previous
#include <cuda_runtime.h>
#include <cstdint>

// ---------------------------------------------------------------------------
// MPEdgeNodeBlock — TF32 mma.sync.  R12: persistent per-layer kernels.
// Each CTA stages the full layer weight matrix (192x196 fp32 = 150KB) in smem
// ONCE, then loops 64-row M-tiles.  Warp tile 32m x 48n (full N=192 in one
// pass): 5 ldsm -> 12 MMAs per k-step (was 0.75 ldsm/MMA, now 0.42) since
// R10 was smem-crossbar-bound, not tensor-bound.
// ---------------------------------------------------------------------------
#define N_NODES  25000
#define NODE_PAD 25024
#define N_EDGES  200000
#define IN_F     64
#define OUT_F    64
#define HDIM     192

// -------------------- scratch (device globals; no runtime alloc) ------------
__device__ __align__(16) float g_Xr[NODE_PAD * HDIM];
__device__ __align__(16) float g_Xi[NODE_PAD * HDIM];
__device__ __align__(16) float g_Xt[NODE_PAD * HDIM];
__device__ __align__(16) float g_Xu[NODE_PAD * HDIM];
__device__ __align__(16) float g_Er[(size_t)N_EDGES * OUT_F];
__device__ __align__(16) float g_Ei[(size_t)N_EDGES * OUT_F];
__device__ __align__(16) float g_Yt[(size_t)N_EDGES * HDIM];
__device__ __align__(16) float g_Yu[(size_t)N_EDGES * HDIM];
__device__ int g_row[N_EDGES];
__device__ int g_col[N_EDGES];
__device__ int g_is64;
#define W_TOTAL 253952
__device__ __align__(16) float g_Wt[W_TOTAL];
#define OFF_WN   0
#define OFF_WE   4096
#define OFF_NW   8192
#define OFF_NOW  118784
#define OFF_EW   131072
#define OFF_EOW  241664

// -------------------- helpers ------------------------------------------------
__device__ __forceinline__ uint32_t smem_u32(const void* p) {
    uint32_t a;
    asm("{ .reg .u64 t; cvta.to.shared.u64 t, %1; cvt.u32.u64 %0, t; }"
        : "=r"(a) : "l"(p));
    return a;
}

__device__ __forceinline__ float tf32r(float f) {
    uint32_t r;
    asm("cvt.rna.tf32.f32 %0, %1;" : "=r"(r) : "f"(f));
    return __uint_as_float(r);
}

__device__ __forceinline__ void ldsm_x4(uint32_t& r0, uint32_t& r1,
                                        uint32_t& r2, uint32_t& r3,
                                        uint32_t addr) {
    asm volatile("ldmatrix.sync.aligned.m8n8.x4.shared.b16 {%0,%1,%2,%3}, [%4];"
                 : "=r"(r0), "=r"(r1), "=r"(r2), "=r"(r3) : "r"(addr));
}

__device__ __forceinline__ void mma_tf32(float* c, const uint32_t* a,
                                         const uint32_t* b) {
    asm volatile(
        "mma.sync.aligned.m16n8k8.row.col.f32.tf32.tf32.f32 "
        "{%0,%1,%2,%3}, {%4,%5,%6,%7}, {%8,%9}, {%0,%1,%2,%3};"
        : "+f"(c[0]), "+f"(c[1]), "+f"(c[2]), "+f"(c[3])
        : "r"(a[0]), "r"(a[1]), "r"(a[2]), "r"(a[3]), "r"(b[0]), "r"(b[1]));
}

__device__ __forceinline__ void cp16(uint32_t dst, const void* src) {
    asm volatile("cp.async.cg.shared.global [%0], [%1], 16;"
                 :: "r"(dst), "l"(src));
}

// -------------------- edge_index dtype detection + conversion ---------------
__global__ void k_detect(const unsigned int* __restrict__ p) {
    if (threadIdx.x == 0) {
        int all_zero = 1;
        for (int i = 0; i < 128; ++i)
            if (p[2 * i + 1] != 0u) { all_zero = 0; break; }
        g_is64 = all_zero;
    }
}

__global__ void k_convert(const void* __restrict__ raw) {
    int e = blockIdx.x * blockDim.x + threadIdx.x;
    if (e >= N_EDGES) return;
    if (g_is64) {
        const long long* p = (const long long*)raw;
        g_row[e] = (int)p[2 * e];
        g_col[e] = (int)p[2 * e + 1];
    } else {
        const int* p = (const int*)raw;
        g_row[e] = p[2 * e];
        g_col[e] = p[2 * e + 1];
    }
}

// -------------------- weight prep: round to tf32 once ------------------------
__global__ void k_prepW(const float* s0, const float* s1, const float* s2,
                        const float* s3, const float* s4, const float* s5) {
    const int sizes[6] = {4096, 4096, 110592, 12288, 110592, 12288};
    const int offs[6]  = {OFF_WN, OFF_WE, OFF_NW, OFF_NOW, OFF_EW, OFF_EOW};
    int t = blockIdx.y;
    const float* s = (t == 0) ? s0 : (t == 1) ? s1 : (t == 2) ? s2
                   : (t == 3) ? s3 : (t == 4) ? s4 : s5;
    for (int i = blockIdx.x * blockDim.x + threadIdx.x; i < sizes[t];
         i += gridDim.x * blockDim.x)
        g_Wt[offs[t] + i] = tf32r(s[i]);
}

__global__ void k_zeroX() {
    int i = blockIdx.x * blockDim.x + threadIdx.x;
    if (i < N_NODES * HDIM) { g_Xr[i] = 0.f; g_Xi[i] = 0.f; }
}

__global__ void k_roundX() {
    int i = blockIdx.x * blockDim.x + threadIdx.x;
    if (i < N_NODES * HDIM) {
        g_Xr[i] = tf32r(g_Xr[i]);
        g_Xi[i] = tf32r(g_Xi[i]);
    }
}

// -------------------- projection GEMM (K=64): C = A @ W^T + b ---------------
__global__ __launch_bounds__(256)
void k_proj(const float* __restrict__ A, int M,
            const float* __restrict__ W,
            const float* __restrict__ bias,
            float* __restrict__ C, int ldc)
{
    constexpr int K = 64, KPAD = 68, vpr = 16;
    extern __shared__ __align__(16) char smem[];
    float* As = reinterpret_cast<float*>(smem);
    float* Bs = As + 64 * KPAD;
    const uint32_t As32 = smem_u32(As);
    const uint32_t Bs32 = smem_u32(Bs);

    const int tid = threadIdx.x, lane = tid & 31, wid = tid >> 5;
    const int wm = wid >> 2, wn = wid & 3;
    const int bm = blockIdx.x * 64;

    for (int idx = tid; idx < 64 * vpr; idx += 256) {
        int row = idx / vpr, c4 = (idx - row * vpr) * 4, gm = bm + row;
        float4 v = make_float4(0.f, 0.f, 0.f, 0.f);
        if (gm < M)
            v = *reinterpret_cast<const float4*>(A + (size_t)gm * K + c4);
        *reinterpret_cast<float4*>(As + row * KPAD + c4) =
            make_float4(tf32r(v.x), tf32r(v.y), tf32r(v.z), tf32r(v.w));
    }
    for (int idx = tid; idx < 64 * vpr; idx += 256) {
        int n = idx / vpr, c4 = (idx - n * vpr) * 4;
        cp16(Bs32 + (uint32_t)((n * KPAD + c4) * 4), W + (size_t)n * K + c4);
    }
    asm volatile("cp.async.commit_group;");
    asm volatile("cp.async.wait_group 0;");
    __syncthreads();

    const uint32_t aAddr = As32 +
        (uint32_t)(((wm * 32 + (lane & 15)) * KPAD + (lane >> 4) * 4) * 4);
    const int nOff = (lane & 7) + ((lane >> 4) & 1) * 8;
    const uint32_t bAddr = Bs32 +
        (uint32_t)(((wn * 16 + nOff) * KPAD + ((lane >> 3) & 1) * 4) * 4);

    float c[2][2][4];
#pragma unroll
    for (int i = 0; i < 2; ++i)
#pragma unroll
        for (int j = 0; j < 2; ++j)
#pragma unroll
            for (int q = 0; q < 4; ++q) c[i][j][q] = 0.f;

#pragma unroll
    for (int ks = 0; ks < K / 8; ++ks) {
        const uint32_t kb = (uint32_t)(ks * 32);
        uint32_t a0[4], a1[4], b[4];
        ldsm_x4(a0[0], a0[1], a0[2], a0[3], aAddr + kb);
        ldsm_x4(a1[0], a1[1], a1[2], a1[3], aAddr + (uint32_t)(16 * KPAD * 4) + kb);
        ldsm_x4(b[0], b[1], b[2], b[3], bAddr + kb);
        mma_tf32(c[0][0], a0, b);
        mma_tf32(c[0][1], a0, b + 2);
        mma_tf32(c[1][0], a1, b);
        mma_tf32(c[1][1], a1, b + 2);
    }

#pragma unroll
    for (int nt = 0; nt < 2; ++nt) {
        int col = wn * 16 + nt * 8 + (lane & 3) * 2;
        float bx = __ldg(bias + col);
        float by = __ldg(bias + col + 1);
#pragma unroll
        for (int mt = 0; mt < 2; ++mt) {
            int row0 = bm + wm * 32 + mt * 16 + (lane >> 2);
            float v0 = tf32r(c[mt][nt][0] + bx);
            float v1 = tf32r(c[mt][nt][1] + by);
            float v2 = tf32r(c[mt][nt][2] + bx);
            float v3 = tf32r(c[mt][nt][3] + by);
            if (row0 < M)
                *reinterpret_cast<float2*>(C + (size_t)row0 * ldc + col) =
                    make_float2(v0, v1);
            if (row0 + 8 < M)
                *reinterpret_cast<float2*>(C + (size_t)(row0 + 8) * ldc + col) =
                    make_float2(v2, v3);
        }
    }
}

// -------------------- persistent MLP layer: C = act(A @ W^T + b) ------------
// W (NOUT x 192, tf32) staged ONCE in smem; CTA loops 64-row tiles.
// NOUT=192: 8 warps 2m x 4n, warp tile 32m x 48n (5 ldsm / 12 mma per ks).
// NOUT=64:  8 warps 2m x 4n, warp tile 32m x 16n (validated R10 shape).
// MODE 0: A via cp.async (pre-rounded).  MODE 1: gather concat(E,H[row],H[col]).
template <int NOUT, int MODE>
__global__ __launch_bounds__(256)
void k_layer(const float* __restrict__ A, int M, int nTiles,
             const float* __restrict__ W,
             const float* __restrict__ bias,
             const float* __restrict__ alphaPtr,
             float* __restrict__ C, int roundOut,
             const float* __restrict__ GH)
{
    constexpr int K = 192, KPAD = 196, vpr = 48;
    constexpr int NW = (NOUT == 192) ? 48 : 16;   // warp n-tile
    constexpr int NB = NW / 16;                   // b-ldsm per ks
    extern __shared__ __align__(16) char smem[];
    float* Ws = reinterpret_cast<float*>(smem);
    float* As = Ws + NOUT * KPAD;
    const uint32_t Ws32 = smem_u32(Ws);
    const uint32_t As32 = smem_u32(As);

    const int tid = threadIdx.x, lane = tid & 31, wid = tid >> 5;
    const int wm = wid >> 2, wn = wid & 3;

    // ---- stage W once per CTA ----
    for (int idx = tid; idx < NOUT * vpr; idx += 256) {
        int n = idx / vpr, c4 = (idx - n * vpr) * 4;
        cp16(Ws32 + (uint32_t)((n * KPAD + c4) * 4), W + (size_t)n * K + c4);
    }
    asm volatile("cp.async.commit_group;");

    const int nOff = (lane & 7) + ((lane >> 4) & 1) * 8;
    const int kcol = ((lane >> 3) & 1) * 4;
    const uint32_t aAddr = As32 +
        (uint32_t)(((wm * 32 + (lane & 15)) * KPAD + (lane >> 4) * 4) * 4);
    uint32_t bAddr[NB];
#pragma unroll
    for (int j = 0; j < NB; ++j)
        bAddr[j] = Ws32 + (uint32_t)(((wn * NW + j * 16 + nOff) * KPAD + kcol) * 4);

    const bool  act = (alphaPtr != nullptr);
    const float al  = act ? __ldg(alphaPtr) : 1.0f;

    for (int t = blockIdx.x; t < nTiles; t += gridDim.x) {
        const int bm = t * 64;

        // ---- stage A tile ----
        if (MODE == 0) {
            for (int idx = tid; idx < 64 * vpr; idx += 256) {
                int row = idx / vpr, c4 = (idx - row * vpr) * 4;
                cp16(As32 + (uint32_t)((row * KPAD + c4) * 4),
                     A + (size_t)(bm + row) * K + c4);
            }
            asm volatile("cp.async.commit_group;");
        } else {
            for (int idx = tid; idx < 64 * vpr; idx += 256) {
                int row = idx / vpr, c4 = (idx - row * vpr) * 4, e = bm + row;
                int seg = c4 >> 6, off = c4 & 63;
                const float* src;
                if (seg == 0) {
                    src = A + (size_t)e * 64 + off;
                } else {
                    int n = (seg == 1) ? __ldg(&g_row[e]) : __ldg(&g_col[e]);
                    src = GH + (size_t)n * 64 + off;
                }
                float4 v = *reinterpret_cast<const float4*>(src);
                *reinterpret_cast<float4*>(As + row * KPAD + c4) =
                    make_float4(tf32r(v.x), tf32r(v.y), tf32r(v.z), tf32r(v.w));
            }
        }
        asm volatile("cp.async.wait_group 0;");
        __syncthreads();

        float c[2][NB * 2][4];
#pragma unroll
        for (int x = 0; x < 2; ++x)
#pragma unroll
            for (int y = 0; y < NB * 2; ++y)
#pragma unroll
                for (int q = 0; q < 4; ++q) c[x][y][q] = 0.f;

#pragma unroll
        for (int ks = 0; ks < 24; ++ks) {
            const uint32_t kb = (uint32_t)(ks * 32);
            uint32_t a0[4], a1[4];
            ldsm_x4(a0[0], a0[1], a0[2], a0[3], aAddr + kb);
            ldsm_x4(a1[0], a1[1], a1[2], a1[3],
                    aAddr + (uint32_t)(16 * KPAD * 4) + kb);
#pragma unroll
            for (int j = 0; j < NB; ++j) {
                uint32_t b[4];
                ldsm_x4(b[0], b[1], b[2], b[3], bAddr[j] + kb);
                mma_tf32(c[0][2 * j + 0], a0, b);
                mma_tf32(c[0][2 * j + 1], a0, b + 2);
                mma_tf32(c[1][2 * j + 0], a1, b);
                mma_tf32(c[1][2 * j + 1], a1, b + 2);
            }
        }

        // ---- epilogue ----
#pragma unroll
        for (int nf = 0; nf < NB * 2; ++nf) {
            int col = wn * NW + nf * 8 + (lane & 3) * 2;
            float bx = __ldg(bias + col);
            float by = __ldg(bias + col + 1);
#pragma unroll
            for (int mf = 0; mf < 2; ++mf) {
                int row0 = bm + wm * 32 + mf * 16 + (lane >> 2);
                float v0 = c[mf][nf][0] + bx;
                float v1 = c[mf][nf][1] + by;
                float v2 = c[mf][nf][2] + bx;
                float v3 = c[mf][nf][3] + by;
                if (act) {
                    v0 = (v0 >= 0.f) ? v0 : al * v0;
                    v1 = (v1 >= 0.f) ? v1 : al * v1;
                    v2 = (v2 >= 0.f) ? v2 : al * v2;
                    v3 = (v3 >= 0.f) ? v3 : al * v3;
                }
                if (roundOut) {
                    v0 = tf32r(v0); v1 = tf32r(v1);
                    v2 = tf32r(v2); v3 = tf32r(v3);
                }
                if (row0 < M)
                    *reinterpret_cast<float2*>(C + (size_t)row0 * NOUT + col) =
                        make_float2(v0, v1);
                if (row0 + 8 < M)
                    *reinterpret_cast<float2*>(C + (size_t)(row0 + 8) * NOUT + col) =
                        make_float2(v2, v3);
            }
        }
        __syncthreads();     // As reuse next tile
    }
}

// -------------------- node aggregation (segment-sum via atomics) ------------
__global__ void k_scatter() {
    int t = blockIdx.x * blockDim.x + threadIdx.x;
    if (t >= N_EDGES * IN_F) return;
    int e = t >> 6;
    int f = t & 63;
    int r = g_row[e];
    int c = g_col[e];

    float vnr = g_Xr[(size_t)c * HDIM + f];
    float vni = g_Xi[(size_t)c * HDIM + f];
    float ver = g_Er[(size_t)e * 64 + f];
    float vei = g_Ei[(size_t)e * 64 + f];

    atomicAdd(&g_Xr[(size_t)r * HDIM + 64  + f], vnr);
    atomicAdd(&g_Xr[(size_t)r * HDIM + 128 + f], ver);
    atomicAdd(&g_Xi[(size_t)r * HDIM + 64  + f], vni);
    atomicAdd(&g_Xi[(size_t)r * HDIM + 128 + f], vei);
}

// ---------------------------------------------------------------------------
static float* symaddr(const void* sym) {
    void* p = nullptr;
    cudaGetSymbolAddress(&p, sym);
    return (float*)p;
}

extern "C" void kernel_launch(void* const* d_in, const int* in_sizes, int n_in,
                              void* d_out, int out_size)
{
    const float* node_real = (const float*)d_in[0];
    const float* node_imag = (const float*)d_in[1];
    const float* edge_real = (const float*)d_in[2];
    const float* edge_imag = (const float*)d_in[3];
    const void*  edge_idx  = d_in[4];
    const float* Wn        = (const float*)d_in[5];
    const float* bn_       = (const float*)d_in[6];
    const float* We        = (const float*)d_in[7];
    const float* be_       = (const float*)d_in[8];
    const float* node_W    = (const float*)d_in[9];
    const float* node_b    = (const float*)d_in[10];
    const float* node_al   = (const float*)d_in[11];
    const float* node_oW   = (const float*)d_in[12];
    const float* node_ob   = (const float*)d_in[13];
    const float* edge_W    = (const float*)d_in[14];
    const float* edge_b    = (const float*)d_in[15];
    const float* edge_al   = (const float*)d_in[16];
    const float* edge_oW   = (const float*)d_in[17];
    const float* edge_ob   = (const float*)d_in[18];

    float* out  = (float*)d_out;
    float* hr   = out;
    float* hi   = out + (size_t)N_NODES * OUT_F;
    float* outr = out + 2 * (size_t)N_NODES * OUT_F;
    float* outi = outr + (size_t)N_EDGES * OUT_F;

    float* Xr = symaddr(g_Xr);
    float* Xi = symaddr(g_Xi);
    float* Xt = symaddr(g_Xt);
    float* Xu = symaddr(g_Xu);
    float* Er = symaddr(g_Er);
    float* Ei = symaddr(g_Ei);
    float* Yt = symaddr(g_Yt);
    float* Yu = symaddr(g_Yu);
    float* Wt = symaddr(g_Wt);

    const int SMEM_PROJ = 128 * 68 * 4;            // 34.8 KB
    const int SMEM_L192 = (192 + 64) * 196 * 4;    // 200.7 KB -> 1 CTA/SM
    const int SMEM_L64  = (64 + 64) * 196 * 4;     // 100.4 KB -> 2 CTA/SM
    cudaFuncSetAttribute(k_proj, cudaFuncAttributeMaxDynamicSharedMemorySize, SMEM_PROJ);
    cudaFuncSetAttribute(k_layer<192, 0>, cudaFuncAttributeMaxDynamicSharedMemorySize, SMEM_L192);
    cudaFuncSetAttribute(k_layer<192, 1>, cudaFuncAttributeMaxDynamicSharedMemorySize, SMEM_L192);
    cudaFuncSetAttribute(k_layer<64, 0>,  cudaFuncAttributeMaxDynamicSharedMemorySize, SMEM_L64);

    const int TPB = 256;
    const int gN  = (N_NODES + 63) / 64;   // 391 tiles
    const int gE  = N_EDGES / 64;          // 3125 tiles
    const int G1  = 148;                   // persistent grid, 1 CTA/SM
    const int G2  = 296;                   // 2 CTA/SM
    const int HH  = HDIM * HDIM;

    // 1-2. edge index conversion
    k_detect<<<1, 32>>>((const unsigned int*)edge_idx);
    k_convert<<<(N_EDGES + TPB - 1) / TPB, TPB>>>(edge_idx);

    // 3. weight prep (tf32 round)
    k_prepW<<<dim3(432, 6), TPB>>>(Wn, We, node_W, node_oW, edge_W, edge_oW);

    // 4. zero node agg buffers
    k_zeroX<<<(N_NODES * HDIM + TPB - 1) / TPB, TPB>>>();

    // 5-8. projections
    k_proj<<<gE, TPB, SMEM_PROJ>>>(edge_real, N_EDGES, Wt + OFF_WE, be_, Er, OUT_F);
    k_proj<<<gE, TPB, SMEM_PROJ>>>(edge_imag, N_EDGES, Wt + OFF_WE, be_, Ei, OUT_F);
    k_proj<<<gN, TPB, SMEM_PROJ>>>(node_real, N_NODES, Wt + OFF_WN, bn_, Xr, HDIM);
    k_proj<<<gN, TPB, SMEM_PROJ>>>(node_imag, N_NODES, Wt + OFF_WN, bn_, Xi, HDIM);

    // 9-10. node aggregation + tf32 round
    k_scatter<<<(N_EDGES * IN_F + TPB - 1) / TPB, TPB>>>();
    k_roundX<<<(N_NODES * HDIM + TPB - 1) / TPB, TPB>>>();

    // 11-14. node MLP (real): Xr -> Xt -> Xu -> Xt -> hr
    k_layer<192, 0><<<G1, TPB, SMEM_L192>>>(Xr, N_NODES, gN, Wt + OFF_NW,        node_b,          node_al,     Xt, 1, nullptr);
    k_layer<192, 0><<<G1, TPB, SMEM_L192>>>(Xt, N_NODES, gN, Wt + OFF_NW + HH,   node_b + HDIM,   node_al + 1, Xu, 1, nullptr);
    k_layer<192, 0><<<G1, TPB, SMEM_L192>>>(Xu, N_NODES, gN, Wt + OFF_NW + 2*HH, node_b + 2*HDIM, node_al + 2, Xt, 1, nullptr);
    k_layer<64, 0><<<G2, TPB, SMEM_L64>>>(Xt, N_NODES, gN, Wt + OFF_NOW, node_ob, nullptr, hr, 0, nullptr);

    // 15-18. node MLP (imag)
    k_layer<192, 0><<<G1, TPB, SMEM_L192>>>(Xi, N_NODES, gN, Wt + OFF_NW,        node_b,          node_al,     Xt, 1, nullptr);
    k_layer<192, 0><<<G1, TPB, SMEM_L192>>>(Xt, N_NODES, gN, Wt + OFF_NW + HH,   node_b + HDIM,   node_al + 1, Xu, 1, nullptr);
    k_layer<192, 0><<<G1, TPB, SMEM_L192>>>(Xu, N_NODES, gN, Wt + OFF_NW + 2*HH, node_b + 2*HDIM, node_al + 2, Xt, 1, nullptr);
    k_layer<64, 0><<<G2, TPB, SMEM_L64>>>(Xt, N_NODES, gN, Wt + OFF_NOW, node_ob, nullptr, hi, 0, nullptr);

    // 19-22. edge MLP (real): gather(Er,hr) -> Yt -> Yu -> Yt -> outr
    k_layer<192, 1><<<G1, TPB, SMEM_L192>>>(Er, N_EDGES, gE, Wt + OFF_EW,        edge_b,          edge_al,     Yt, 1, hr);
    k_layer<192, 0><<<G1, TPB, SMEM_L192>>>(Yt, N_EDGES, gE, Wt + OFF_EW + HH,   edge_b + HDIM,   edge_al + 1, Yu, 1, nullptr);
    k_layer<192, 0><<<G1, TPB, SMEM_L192>>>(Yu, N_EDGES, gE, Wt + OFF_EW + 2*HH, edge_b + 2*HDIM, edge_al + 2, Yt, 1, nullptr);
    k_layer<64, 0><<<G2, TPB, SMEM_L64>>>(Yt, N_EDGES, gE, Wt + OFF_EOW, edge_ob, nullptr, outr, 0, nullptr);

    // 23-26. edge MLP (imag)
    k_layer<192, 1><<<G1, TPB, SMEM_L192>>>(Ei, N_EDGES, gE, Wt + OFF_EW,        edge_b,          edge_al,     Yt, 1, hi);
    k_layer<192, 0><<<G1, TPB, SMEM_L192>>>(Yt, N_EDGES, gE, Wt + OFF_EW + HH,   edge_b + HDIM,   edge_al + 1, Yu, 1, nullptr);
    k_layer<192, 0><<<G1, TPB, SMEM_L192>>>(Yu, N_EDGES, gE, Wt + OFF_EW + 2*HH, edge_b + 2*HDIM, edge_al + 2, Yt, 1, nullptr);
    k_layer<64, 0><<<G2, TPB, SMEM_L64>>>(Yt, N_EDGES, gE, Wt + OFF_EOW, edge_ob, nullptr, outi, 0, nullptr);
}

// round 14
// speedup vs baseline: 1.3254x; 1.2024x over previous
#include <cuda_runtime.h>
#include <cstdint>

// ---------------------------------------------------------------------------
// MPEdgeNodeBlock — TF32 mma.sync.  R13: K-chunked double-buffered layers.
// Per 64-row tile: loop K in 48-chunks, staging A(64x48)+B(192x48) via
// cp.async, accumulating full 192-wide output in registers (warp tile
// 32m x 48n).  106.5KB smem -> 2 CTAs/SM (16 warps) AND low crossbar
// traffic (R10 had 2 CTA/SM but 1.8x crossbar traffic; R12 had low traffic
// but 1 CTA/SM — both ~1475-1492us).
// ---------------------------------------------------------------------------
#define N_NODES  25000
#define NODE_PAD 25024
#define N_EDGES  200000
#define IN_F     64
#define OUT_F    64
#define HDIM     192

// -------------------- scratch (device globals; no runtime alloc) ------------
__device__ __align__(16) float g_Xr[NODE_PAD * HDIM];
__device__ __align__(16) float g_Xi[NODE_PAD * HDIM];
__device__ __align__(16) float g_Xt[NODE_PAD * HDIM];
__device__ __align__(16) float g_Xu[NODE_PAD * HDIM];
__device__ __align__(16) float g_Er[(size_t)N_EDGES * OUT_F];
__device__ __align__(16) float g_Ei[(size_t)N_EDGES * OUT_F];
__device__ __align__(16) float g_Yt[(size_t)N_EDGES * HDIM];
__device__ __align__(16) float g_Yu[(size_t)N_EDGES * HDIM];
__device__ int g_row[N_EDGES];
__device__ int g_col[N_EDGES];
__device__ int g_is64;
#define W_TOTAL 253952
__device__ __align__(16) float g_Wt[W_TOTAL];
#define OFF_WN   0
#define OFF_WE   4096
#define OFF_NW   8192
#define OFF_NOW  118784
#define OFF_EW   131072
#define OFF_EOW  241664

// -------------------- helpers ------------------------------------------------
__device__ __forceinline__ uint32_t smem_u32(const void* p) {
    uint32_t a;
    asm("{ .reg .u64 t; cvta.to.shared.u64 t, %1; cvt.u32.u64 %0, t; }"
        : "=r"(a) : "l"(p));
    return a;
}

__device__ __forceinline__ float tf32r(float f) {
    uint32_t r;
    asm("cvt.rna.tf32.f32 %0, %1;" : "=r"(r) : "f"(f));
    return __uint_as_float(r);
}

__device__ __forceinline__ void ldsm_x4(uint32_t& r0, uint32_t& r1,
                                        uint32_t& r2, uint32_t& r3,
                                        uint32_t addr) {
    asm volatile("ldmatrix.sync.aligned.m8n8.x4.shared.b16 {%0,%1,%2,%3}, [%4];"
                 : "=r"(r0), "=r"(r1), "=r"(r2), "=r"(r3) : "r"(addr));
}

__device__ __forceinline__ void mma_tf32(float* c, const uint32_t* a,
                                         const uint32_t* b) {
    asm volatile(
        "mma.sync.aligned.m16n8k8.row.col.f32.tf32.tf32.f32 "
        "{%0,%1,%2,%3}, {%4,%5,%6,%7}, {%8,%9}, {%0,%1,%2,%3};"
        : "+f"(c[0]), "+f"(c[1]), "+f"(c[2]), "+f"(c[3])
        : "r"(a[0]), "r"(a[1]), "r"(a[2]), "r"(a[3]), "r"(b[0]), "r"(b[1]));
}

__device__ __forceinline__ void cp16(uint32_t dst, const void* src) {
    asm volatile("cp.async.cg.shared.global [%0], [%1], 16;"
                 :: "r"(dst), "l"(src));
}

// -------------------- edge_index dtype detection + conversion ---------------
__global__ void k_detect(const unsigned int* __restrict__ p) {
    if (threadIdx.x == 0) {
        int all_zero = 1;
        for (int i = 0; i < 128; ++i)
            if (p[2 * i + 1] != 0u) { all_zero = 0; break; }
        g_is64 = all_zero;
    }
}

__global__ void k_convert(const void* __restrict__ raw) {
    int e = blockIdx.x * blockDim.x + threadIdx.x;
    if (e >= N_EDGES) return;
    if (g_is64) {
        const long long* p = (const long long*)raw;
        g_row[e] = (int)p[2 * e];
        g_col[e] = (int)p[2 * e + 1];
    } else {
        const int* p = (const int*)raw;
        g_row[e] = p[2 * e];
        g_col[e] = p[2 * e + 1];
    }
}

// -------------------- weight prep: round to tf32 once ------------------------
__global__ void k_prepW(const float* s0, const float* s1, const float* s2,
                        const float* s3, const float* s4, const float* s5) {
    const int sizes[6] = {4096, 4096, 110592, 12288, 110592, 12288};
    const int offs[6]  = {OFF_WN, OFF_WE, OFF_NW, OFF_NOW, OFF_EW, OFF_EOW};
    int t = blockIdx.y;
    const float* s = (t == 0) ? s0 : (t == 1) ? s1 : (t == 2) ? s2
                   : (t == 3) ? s3 : (t == 4) ? s4 : s5;
    for (int i = blockIdx.x * blockDim.x + threadIdx.x; i < sizes[t];
         i += gridDim.x * blockDim.x)
        g_Wt[offs[t] + i] = tf32r(s[i]);
}

__global__ void k_zeroX() {
    int i = blockIdx.x * blockDim.x + threadIdx.x;
    if (i < N_NODES * HDIM) { g_Xr[i] = 0.f; g_Xi[i] = 0.f; }
}

__global__ void k_roundX() {
    int i = blockIdx.x * blockDim.x + threadIdx.x;
    if (i < N_NODES * HDIM) {
        g_Xr[i] = tf32r(g_Xr[i]);
        g_Xi[i] = tf32r(g_Xi[i]);
    }
}

// -------------------- projection GEMM (K=64): C = A @ W^T + b ---------------
__global__ __launch_bounds__(256)
void k_proj(const float* __restrict__ A, int M,
            const float* __restrict__ W,
            const float* __restrict__ bias,
            float* __restrict__ C, int ldc)
{
    constexpr int K = 64, KPAD = 68, vpr = 16;
    extern __shared__ __align__(16) char smem[];
    float* As = reinterpret_cast<float*>(smem);
    float* Bs = As + 64 * KPAD;
    const uint32_t As32 = smem_u32(As);
    const uint32_t Bs32 = smem_u32(Bs);

    const int tid = threadIdx.x, lane = tid & 31, wid = tid >> 5;
    const int wm = wid >> 2, wn = wid & 3;
    const int bm = blockIdx.x * 64;

    for (int idx = tid; idx < 64 * vpr; idx += 256) {
        int row = idx / vpr, c4 = (idx - row * vpr) * 4, gm = bm + row;
        float4 v = make_float4(0.f, 0.f, 0.f, 0.f);
        if (gm < M)
            v = *reinterpret_cast<const float4*>(A + (size_t)gm * K + c4);
        *reinterpret_cast<float4*>(As + row * KPAD + c4) =
            make_float4(tf32r(v.x), tf32r(v.y), tf32r(v.z), tf32r(v.w));
    }
    for (int idx = tid; idx < 64 * vpr; idx += 256) {
        int n = idx / vpr, c4 = (idx - n * vpr) * 4;
        cp16(Bs32 + (uint32_t)((n * KPAD + c4) * 4), W + (size_t)n * K + c4);
    }
    asm volatile("cp.async.commit_group;");
    asm volatile("cp.async.wait_group 0;");
    __syncthreads();

    const uint32_t aAddr = As32 +
        (uint32_t)(((wm * 32 + (lane & 15)) * KPAD + (lane >> 4) * 4) * 4);
    const int nOff = (lane & 7) + ((lane >> 4) & 1) * 8;
    const uint32_t bAddr = Bs32 +
        (uint32_t)(((wn * 16 + nOff) * KPAD + ((lane >> 3) & 1) * 4) * 4);

    float c[2][2][4];
#pragma unroll
    for (int i = 0; i < 2; ++i)
#pragma unroll
        for (int j = 0; j < 2; ++j)
#pragma unroll
            for (int q = 0; q < 4; ++q) c[i][j][q] = 0.f;

#pragma unroll
    for (int ks = 0; ks < K / 8; ++ks) {
        const uint32_t kb = (uint32_t)(ks * 32);
        uint32_t a0[4], a1[4], b[4];
        ldsm_x4(a0[0], a0[1], a0[2], a0[3], aAddr + kb);
        ldsm_x4(a1[0], a1[1], a1[2], a1[3], aAddr + (uint32_t)(16 * KPAD * 4) + kb);
        ldsm_x4(b[0], b[1], b[2], b[3], bAddr + kb);
        mma_tf32(c[0][0], a0, b);
        mma_tf32(c[0][1], a0, b + 2);
        mma_tf32(c[1][0], a1, b);
        mma_tf32(c[1][1], a1, b + 2);
    }

#pragma unroll
    for (int nt = 0; nt < 2; ++nt) {
        int col = wn * 16 + nt * 8 + (lane & 3) * 2;
        float bx = __ldg(bias + col);
        float by = __ldg(bias + col + 1);
#pragma unroll
        for (int mt = 0; mt < 2; ++mt) {
            int row0 = bm + wm * 32 + mt * 16 + (lane >> 2);
            float v0 = tf32r(c[mt][nt][0] + bx);
            float v1 = tf32r(c[mt][nt][1] + by);
            float v2 = tf32r(c[mt][nt][2] + bx);
            float v3 = tf32r(c[mt][nt][3] + by);
            if (row0 < M)
                *reinterpret_cast<float2*>(C + (size_t)row0 * ldc + col) =
                    make_float2(v0, v1);
            if (row0 + 8 < M)
                *reinterpret_cast<float2*>(C + (size_t)(row0 + 8) * ldc + col) =
                    make_float2(v2, v3);
        }
    }
}

// -------------------- K-chunked MLP layer: C = act(A @ W^T + b) -------------
// K=192 in 4 chunks of 48.  Per chunk stage A(64x48)+B(NOUTx48) into smem
// (double buffered, cp.async), warp tile 32m x (NOUT/4)n, acc in regs.
// MODE 0: A via cp.async (pre-rounded).  MODE 1: gather concat(E,H[row],H[col]).
template <int NOUT, int MODE>
__global__ __launch_bounds__(256, 2)
void k_layer(const float* __restrict__ A, int M,
             const float* __restrict__ W,
             const float* __restrict__ bias,
             const float* __restrict__ alphaPtr,
             float* __restrict__ C, int roundOut,
             const float* __restrict__ GH)
{
    constexpr int K = 192, KC = 48, KCPAD = 52, NCH = K / KC;
    constexpr int NW = NOUT / 4;                  // warp n-tile (48 or 16)
    constexpr int NB = NW / 16;                   // b-ldsm per ks (3 or 1)
    constexpr int CHF = (64 + NOUT) * KCPAD;      // floats per buffer
    extern __shared__ __align__(16) char smem[];
    float* buf0 = reinterpret_cast<float*>(smem);

    const int tid = threadIdx.x, lane = tid & 31, wid = tid >> 5;
    const int wm = wid >> 2, wn = wid & 3;
    const int bm = blockIdx.x * 64;

    // ---- chunk staging ----
    auto stage = [&](int c, int b) {
        float* bufA = buf0 + b * CHF;
        float* bufB = bufA + 64 * KCPAD;
        const uint32_t A32 = smem_u32(bufA);
        const uint32_t B32 = smem_u32(bufB);
        if (MODE == 0) {
#pragma unroll
            for (int it = 0; it < 3; ++it) {
                int idx = tid + it * 256;          // 0..767
                int row = idx / 12, q = idx - row * 12;
                cp16(A32 + (uint32_t)((row * KCPAD + q * 4) * 4),
                     A + (size_t)(bm + row) * K + c * KC + q * 4);
            }
        } else {
#pragma unroll
            for (int it = 0; it < 3; ++it) {
                int idx = tid + it * 256;
                int row = idx / 12, q = idx - row * 12;
                int e = bm + row;
                int gcol = c * KC + q * 4;
                int seg = gcol >> 6, off = gcol & 63;
                const float* src;
                if (seg == 0) {
                    src = A + (size_t)e * 64 + off;
                } else {
                    int n = (seg == 1) ? __ldg(&g_row[e]) : __ldg(&g_col[e]);
                    src = GH + (size_t)n * 64 + off;
                }
                float4 v = *reinterpret_cast<const float4*>(src);
                *reinterpret_cast<float4*>(bufA + row * KCPAD + q * 4) =
                    make_float4(tf32r(v.x), tf32r(v.y), tf32r(v.z), tf32r(v.w));
            }
        }
#pragma unroll
        for (int it = 0; it < NOUT * 12 / 256; ++it) {
            int idx = tid + it * 256;
            int n = idx / 12, q = idx - n * 12;
            cp16(B32 + (uint32_t)((n * KCPAD + q * 4) * 4),
                 W + (size_t)n * K + c * KC + q * 4);
        }
        asm volatile("cp.async.commit_group;");
    };

    // lane addressing (chunk-local, validated mapping from R10)
    const uint32_t aLaneOff =
        (uint32_t)(((wm * 32 + (lane & 15)) * KCPAD + (lane >> 4) * 4) * 4);
    const int nOff = (lane & 7) + ((lane >> 4) & 1) * 8;
    const int kcol = ((lane >> 3) & 1) * 4;
    uint32_t bLaneOff[NB];
#pragma unroll
    for (int j = 0; j < NB; ++j)
        bLaneOff[j] = (uint32_t)(((wn * NW + j * 16 + nOff) * KCPAD + kcol) * 4);

    float acc[2][NB * 2][4];
#pragma unroll
    for (int x = 0; x < 2; ++x)
#pragma unroll
        for (int y = 0; y < NB * 2; ++y)
#pragma unroll
            for (int q = 0; q < 4; ++q) acc[x][y][q] = 0.f;

    stage(0, 0);

#pragma unroll
    for (int c = 0; c < NCH; ++c) {
        if (c + 1 < NCH) {
            stage(c + 1, (c + 1) & 1);
            asm volatile("cp.async.wait_group 1;");
        } else {
            asm volatile("cp.async.wait_group 0;");
        }
        __syncthreads();

        float* bufA = buf0 + (c & 1) * CHF;
        const uint32_t A32 = smem_u32(bufA);
        const uint32_t B32 = smem_u32(bufA + 64 * KCPAD);
        const uint32_t aAddr = A32 + aLaneOff;

#pragma unroll
        for (int ks = 0; ks < KC / 8; ++ks) {
            const uint32_t kb = (uint32_t)(ks * 32);
            uint32_t a0[4], a1[4];
            ldsm_x4(a0[0], a0[1], a0[2], a0[3], aAddr + kb);
            ldsm_x4(a1[0], a1[1], a1[2], a1[3],
                    aAddr + (uint32_t)(16 * KCPAD * 4) + kb);
#pragma unroll
            for (int j = 0; j < NB; ++j) {
                uint32_t b[4];
                ldsm_x4(b[0], b[1], b[2], b[3], B32 + bLaneOff[j] + kb);
                mma_tf32(acc[0][2 * j + 0], a0, b);
                mma_tf32(acc[0][2 * j + 1], a0, b + 2);
                mma_tf32(acc[1][2 * j + 0], a1, b);
                mma_tf32(acc[1][2 * j + 1], a1, b + 2);
            }
        }
        __syncthreads();
    }

    // ---- epilogue ----
    const bool  act = (alphaPtr != nullptr);
    const float al  = act ? __ldg(alphaPtr) : 1.0f;
#pragma unroll
    for (int nf = 0; nf < NB * 2; ++nf) {
        int col = wn * NW + nf * 8 + (lane & 3) * 2;
        float bx = __ldg(bias + col);
        float by = __ldg(bias + col + 1);
#pragma unroll
        for (int mf = 0; mf < 2; ++mf) {
            int row0 = bm + wm * 32 + mf * 16 + (lane >> 2);
            float v0 = acc[mf][nf][0] + bx;
            float v1 = acc[mf][nf][1] + by;
            float v2 = acc[mf][nf][2] + bx;
            float v3 = acc[mf][nf][3] + by;
            if (act) {
                v0 = (v0 >= 0.f) ? v0 : al * v0;
                v1 = (v1 >= 0.f) ? v1 : al * v1;
                v2 = (v2 >= 0.f) ? v2 : al * v2;
                v3 = (v3 >= 0.f) ? v3 : al * v3;
            }
            if (roundOut) {
                v0 = tf32r(v0); v1 = tf32r(v1);
                v2 = tf32r(v2); v3 = tf32r(v3);
            }
            if (row0 < M)
                *reinterpret_cast<float2*>(C + (size_t)row0 * NOUT + col) =
                    make_float2(v0, v1);
            if (row0 + 8 < M)
                *reinterpret_cast<float2*>(C + (size_t)(row0 + 8) * NOUT + col) =
                    make_float2(v2, v3);
        }
    }
}

// -------------------- node aggregation (segment-sum via atomics) ------------
__global__ void k_scatter() {
    int t = blockIdx.x * blockDim.x + threadIdx.x;
    if (t >= N_EDGES * IN_F) return;
    int e = t >> 6;
    int f = t & 63;
    int r = g_row[e];
    int c = g_col[e];

    float vnr = g_Xr[(size_t)c * HDIM + f];
    float vni = g_Xi[(size_t)c * HDIM + f];
    float ver = g_Er[(size_t)e * 64 + f];
    float vei = g_Ei[(size_t)e * 64 + f];

    atomicAdd(&g_Xr[(size_t)r * HDIM + 64  + f], vnr);
    atomicAdd(&g_Xr[(size_t)r * HDIM + 128 + f], ver);
    atomicAdd(&g_Xi[(size_t)r * HDIM + 64  + f], vni);
    atomicAdd(&g_Xi[(size_t)r * HDIM + 128 + f], vei);
}

// ---------------------------------------------------------------------------
static float* symaddr(const void* sym) {
    void* p = nullptr;
    cudaGetSymbolAddress(&p, sym);
    return (float*)p;
}

extern "C" void kernel_launch(void* const* d_in, const int* in_sizes, int n_in,
                              void* d_out, int out_size)
{
    const float* node_real = (const float*)d_in[0];
    const float* node_imag = (const float*)d_in[1];
    const float* edge_real = (const float*)d_in[2];
    const float* edge_imag = (const float*)d_in[3];
    const void*  edge_idx  = d_in[4];
    const float* Wn        = (const float*)d_in[5];
    const float* bn_       = (const float*)d_in[6];
    const float* We        = (const float*)d_in[7];
    const float* be_       = (const float*)d_in[8];
    const float* node_W    = (const float*)d_in[9];
    const float* node_b    = (const float*)d_in[10];
    const float* node_al   = (const float*)d_in[11];
    const float* node_oW   = (const float*)d_in[12];
    const float* node_ob   = (const float*)d_in[13];
    const float* edge_W    = (const float*)d_in[14];
    const float* edge_b    = (const float*)d_in[15];
    const float* edge_al   = (const float*)d_in[16];
    const float* edge_oW   = (const float*)d_in[17];
    const float* edge_ob   = (const float*)d_in[18];

    float* out  = (float*)d_out;
    float* hr   = out;
    float* hi   = out + (size_t)N_NODES * OUT_F;
    float* outr = out + 2 * (size_t)N_NODES * OUT_F;
    float* outi = outr + (size_t)N_EDGES * OUT_F;

    float* Xr = symaddr(g_Xr);
    float* Xi = symaddr(g_Xi);
    float* Xt = symaddr(g_Xt);
    float* Xu = symaddr(g_Xu);
    float* Er = symaddr(g_Er);
    float* Ei = symaddr(g_Ei);
    float* Yt = symaddr(g_Yt);
    float* Yu = symaddr(g_Yu);
    float* Wt = symaddr(g_Wt);

    const int SMEM_PROJ = 128 * 68 * 4;                 // 34.8 KB
    const int SMEM_L192 = 2 * (64 + 192) * 52 * 4;      // 106.5 KB -> 2 CTA/SM
    const int SMEM_L64  = 2 * (64 + 64) * 52 * 4;       // 53.2 KB
    cudaFuncSetAttribute(k_proj, cudaFuncAttributeMaxDynamicSharedMemorySize, SMEM_PROJ);
    cudaFuncSetAttribute(k_layer<192, 0>, cudaFuncAttributeMaxDynamicSharedMemorySize, SMEM_L192);
    cudaFuncSetAttribute(k_layer<192, 1>, cudaFuncAttributeMaxDynamicSharedMemorySize, SMEM_L192);
    cudaFuncSetAttribute(k_layer<64, 0>,  cudaFuncAttributeMaxDynamicSharedMemorySize, SMEM_L64);

    const int TPB = 256;
    const int gN  = (N_NODES + 63) / 64;   // 391
    const int gE  = N_EDGES / 64;          // 3125
    const int HH  = HDIM * HDIM;

    // 1-2. edge index conversion
    k_detect<<<1, 32>>>((const unsigned int*)edge_idx);
    k_convert<<<(N_EDGES + TPB - 1) / TPB, TPB>>>(edge_idx);

    // 3. weight prep (tf32 round)
    k_prepW<<<dim3(432, 6), TPB>>>(Wn, We, node_W, node_oW, edge_W, edge_oW);

    // 4. zero node agg buffers
    k_zeroX<<<(N_NODES * HDIM + TPB - 1) / TPB, TPB>>>();

    // 5-8. projections
    k_proj<<<gE, TPB, SMEM_PROJ>>>(edge_real, N_EDGES, Wt + OFF_WE, be_, Er, OUT_F);
    k_proj<<<gE, TPB, SMEM_PROJ>>>(edge_imag, N_EDGES, Wt + OFF_WE, be_, Ei, OUT_F);
    k_proj<<<gN, TPB, SMEM_PROJ>>>(node_real, N_NODES, Wt + OFF_WN, bn_, Xr, HDIM);
    k_proj<<<gN, TPB, SMEM_PROJ>>>(node_imag, N_NODES, Wt + OFF_WN, bn_, Xi, HDIM);

    // 9-10. node aggregation + tf32 round
    k_scatter<<<(N_EDGES * IN_F + TPB - 1) / TPB, TPB>>>();
    k_roundX<<<(N_NODES * HDIM + TPB - 1) / TPB, TPB>>>();

    // 11-14. node MLP (real): Xr -> Xt -> Xu -> Xt -> hr
    k_layer<192, 0><<<gN, TPB, SMEM_L192>>>(Xr, N_NODES, Wt + OFF_NW,        node_b,          node_al,     Xt, 1, nullptr);
    k_layer<192, 0><<<gN, TPB, SMEM_L192>>>(Xt, N_NODES, Wt + OFF_NW + HH,   node_b + HDIM,   node_al + 1, Xu, 1, nullptr);
    k_layer<192, 0><<<gN, TPB, SMEM_L192>>>(Xu, N_NODES, Wt + OFF_NW + 2*HH, node_b + 2*HDIM, node_al + 2, Xt, 1, nullptr);
    k_layer<64, 0><<<gN, TPB, SMEM_L64>>>(Xt, N_NODES, Wt + OFF_NOW, node_ob, nullptr, hr, 0, nullptr);

    // 15-18. node MLP (imag)
    k_layer<192, 0><<<gN, TPB, SMEM_L192>>>(Xi, N_NODES, Wt + OFF_NW,        node_b,          node_al,     Xt, 1, nullptr);
    k_layer<192, 0><<<gN, TPB, SMEM_L192>>>(Xt, N_NODES, Wt + OFF_NW + HH,   node_b + HDIM,   node_al + 1, Xu, 1, nullptr);
    k_layer<192, 0><<<gN, TPB, SMEM_L192>>>(Xu, N_NODES, Wt + OFF_NW + 2*HH, node_b + 2*HDIM, node_al + 2, Xt, 1, nullptr);
    k_layer<64, 0><<<gN, TPB, SMEM_L64>>>(Xt, N_NODES, Wt + OFF_NOW, node_ob, nullptr, hi, 0, nullptr);

    // 19-22. edge MLP (real): gather(Er,hr) -> Yt -> Yu -> Yt -> outr
    k_layer<192, 1><<<gE, TPB, SMEM_L192>>>(Er, N_EDGES, Wt + OFF_EW,        edge_b,          edge_al,     Yt, 1, hr);
    k_layer<192, 0><<<gE, TPB, SMEM_L192>>>(Yt, N_EDGES, Wt + OFF_EW + HH,   edge_b + HDIM,   edge_al + 1, Yu, 1, nullptr);
    k_layer<192, 0><<<gE, TPB, SMEM_L192>>>(Yu, N_EDGES, Wt + OFF_EW + 2*HH, edge_b + 2*HDIM, edge_al + 2, Yt, 1, nullptr);
    k_layer<64, 0><<<gE, TPB, SMEM_L64>>>(Yt, N_EDGES, Wt + OFF_EOW, edge_ob, nullptr, outr, 0, nullptr);

    // 23-26. edge MLP (imag)
    k_layer<192, 1><<<gE, TPB, SMEM_L192>>>(Ei, N_EDGES, Wt + OFF_EW,        edge_b,          edge_al,     Yt, 1, hi);
    k_layer<192, 0><<<gE, TPB, SMEM_L192>>>(Yt, N_EDGES, Wt + OFF_EW + HH,   edge_b + HDIM,   edge_al + 1, Yu, 1, nullptr);
    k_layer<192, 0><<<gE, TPB, SMEM_L192>>>(Yu, N_EDGES, Wt + OFF_EW + 2*HH, edge_b + 2*HDIM, edge_al + 2, Yt, 1, nullptr);
    k_layer<64, 0><<<gE, TPB, SMEM_L64>>>(Yt, N_EDGES, Wt + OFF_EOW, edge_ob, nullptr, outi, 0, nullptr);
}

// round 15
// speedup vs baseline: 1.4282x; 1.0776x over previous
#include <cuda_runtime.h>
#include <cstdint>

// ---------------------------------------------------------------------------
// MPEdgeNodeBlock — TF32 mma.sync, K-chunked double-buffered layers (R13) +
// R14: merged real/imag in every launch, merged projection kernel, roundX
// folded into node layer-1 staging, partial zeroX.
// ---------------------------------------------------------------------------
#define N_NODES  25000
#define NODE_PAD 25024
#define N_EDGES  200000
#define IN_F     64
#define OUT_F    64
#define HDIM     192

// -------------------- scratch (device globals; no runtime alloc) ------------
__device__ __align__(16) float g_Xr[NODE_PAD * HDIM];
__device__ __align__(16) float g_Xi[NODE_PAD * HDIM];
__device__ __align__(16) float g_Xt[NODE_PAD * HDIM];
__device__ __align__(16) float g_Xu[NODE_PAD * HDIM];
__device__ __align__(16) float g_Xt2[NODE_PAD * HDIM];
__device__ __align__(16) float g_Xu2[NODE_PAD * HDIM];
__device__ __align__(16) float g_Er[(size_t)N_EDGES * OUT_F];
__device__ __align__(16) float g_Ei[(size_t)N_EDGES * OUT_F];
__device__ __align__(16) float g_Yt[(size_t)N_EDGES * HDIM];
__device__ __align__(16) float g_Yu[(size_t)N_EDGES * HDIM];
__device__ __align__(16) float g_Zt[(size_t)N_EDGES * HDIM];
__device__ __align__(16) float g_Zu[(size_t)N_EDGES * HDIM];
__device__ int g_row[N_EDGES];
__device__ int g_col[N_EDGES];
__device__ int g_is64;
#define W_TOTAL 253952
__device__ __align__(16) float g_Wt[W_TOTAL];
#define OFF_WN   0
#define OFF_WE   4096
#define OFF_NW   8192
#define OFF_NOW  118784
#define OFF_EW   131072
#define OFF_EOW  241664

// -------------------- helpers ------------------------------------------------
__device__ __forceinline__ uint32_t smem_u32(const void* p) {
    uint32_t a;
    asm("{ .reg .u64 t; cvta.to.shared.u64 t, %1; cvt.u32.u64 %0, t; }"
        : "=r"(a) : "l"(p));
    return a;
}

__device__ __forceinline__ float tf32r(float f) {
    uint32_t r;
    asm("cvt.rna.tf32.f32 %0, %1;" : "=r"(r) : "f"(f));
    return __uint_as_float(r);
}

__device__ __forceinline__ void ldsm_x4(uint32_t& r0, uint32_t& r1,
                                        uint32_t& r2, uint32_t& r3,
                                        uint32_t addr) {
    asm volatile("ldmatrix.sync.aligned.m8n8.x4.shared.b16 {%0,%1,%2,%3}, [%4];"
                 : "=r"(r0), "=r"(r1), "=r"(r2), "=r"(r3) : "r"(addr));
}

__device__ __forceinline__ void mma_tf32(float* c, const uint32_t* a,
                                         const uint32_t* b) {
    asm volatile(
        "mma.sync.aligned.m16n8k8.row.col.f32.tf32.tf32.f32 "
        "{%0,%1,%2,%3}, {%4,%5,%6,%7}, {%8,%9}, {%0,%1,%2,%3};"
        : "+f"(c[0]), "+f"(c[1]), "+f"(c[2]), "+f"(c[3])
        : "r"(a[0]), "r"(a[1]), "r"(a[2]), "r"(a[3]), "r"(b[0]), "r"(b[1]));
}

__device__ __forceinline__ void cp16(uint32_t dst, const void* src) {
    asm volatile("cp.async.cg.shared.global [%0], [%1], 16;"
                 :: "r"(dst), "l"(src));
}

// -------------------- edge_index dtype detection + conversion ---------------
__global__ void k_detect(const unsigned int* __restrict__ p) {
    if (threadIdx.x == 0) {
        int all_zero = 1;
        for (int i = 0; i < 128; ++i)
            if (p[2 * i + 1] != 0u) { all_zero = 0; break; }
        g_is64 = all_zero;
    }
}

__global__ void k_convert(const void* __restrict__ raw) {
    int e = blockIdx.x * blockDim.x + threadIdx.x;
    if (e >= N_EDGES) return;
    if (g_is64) {
        const long long* p = (const long long*)raw;
        g_row[e] = (int)p[2 * e];
        g_col[e] = (int)p[2 * e + 1];
    } else {
        const int* p = (const int*)raw;
        g_row[e] = p[2 * e];
        g_col[e] = p[2 * e + 1];
    }
}

// -------------------- weight prep: round to tf32 once ------------------------
__global__ void k_prepW(const float* s0, const float* s1, const float* s2,
                        const float* s3, const float* s4, const float* s5) {
    const int sizes[6] = {4096, 4096, 110592, 12288, 110592, 12288};
    const int offs[6]  = {OFF_WN, OFF_WE, OFF_NW, OFF_NOW, OFF_EW, OFF_EOW};
    int t = blockIdx.y;
    const float* s = (t == 0) ? s0 : (t == 1) ? s1 : (t == 2) ? s2
                   : (t == 3) ? s3 : (t == 4) ? s4 : s5;
    for (int i = blockIdx.x * blockDim.x + threadIdx.x; i < sizes[t];
         i += gridDim.x * blockDim.x)
        g_Wt[offs[t] + i] = tf32r(s[i]);
}

// zero only cols 64:192 (projection overwrites cols 0:64)
__global__ void k_zeroX() {
    int i = blockIdx.x * blockDim.x + threadIdx.x;
    if (i < N_NODES * 128) {
        int node = i >> 7, f = i & 127;
        g_Xr[(size_t)node * HDIM + 64 + f] = 0.f;
        g_Xi[(size_t)node * HDIM + 64 + f] = 0.f;
    }
}

// -------------------- merged projection (K=64): real+imag per CTA -----------
__global__ __launch_bounds__(256)
void k_proj2(const float* __restrict__ Ar, const float* __restrict__ Ai,
             int M, const float* __restrict__ W,
             const float* __restrict__ bias,
             float* __restrict__ Cr, float* __restrict__ Ci, int ldc)
{
    constexpr int K = 64, KPAD = 68, vpr = 16;
    extern __shared__ __align__(16) char smem[];
    float* As0 = reinterpret_cast<float*>(smem);
    float* As1 = As0 + 64 * KPAD;
    float* Bs  = As1 + 64 * KPAD;
    const uint32_t Bs32 = smem_u32(Bs);

    const int tid = threadIdx.x, lane = tid & 31, wid = tid >> 5;
    const int wm = wid >> 2, wn = wid & 3;
    const int bm = blockIdx.x * 64;

    // B via cp.async (pre-rounded W)
    for (int idx = tid; idx < 64 * vpr; idx += 256) {
        int n = idx / vpr, c4 = (idx - n * vpr) * 4;
        cp16(Bs32 + (uint32_t)((n * KPAD + c4) * 4), W + (size_t)n * K + c4);
    }
    asm volatile("cp.async.commit_group;");

    // A real + imag, cvt-staged
    for (int idx = tid; idx < 64 * vpr; idx += 256) {
        int row = idx / vpr, c4 = (idx - row * vpr) * 4, gm = bm + row;
        float4 vr = make_float4(0.f, 0.f, 0.f, 0.f);
        float4 vi = make_float4(0.f, 0.f, 0.f, 0.f);
        if (gm < M) {
            vr = *reinterpret_cast<const float4*>(Ar + (size_t)gm * K + c4);
            vi = *reinterpret_cast<const float4*>(Ai + (size_t)gm * K + c4);
        }
        *reinterpret_cast<float4*>(As0 + row * KPAD + c4) =
            make_float4(tf32r(vr.x), tf32r(vr.y), tf32r(vr.z), tf32r(vr.w));
        *reinterpret_cast<float4*>(As1 + row * KPAD + c4) =
            make_float4(tf32r(vi.x), tf32r(vi.y), tf32r(vi.z), tf32r(vi.w));
    }
    asm volatile("cp.async.wait_group 0;");
    __syncthreads();

    const int nOff = (lane & 7) + ((lane >> 4) & 1) * 8;
    const uint32_t bAddr = Bs32 +
        (uint32_t)(((wn * 16 + nOff) * KPAD + ((lane >> 3) & 1) * 4) * 4);
    const uint32_t aLane =
        (uint32_t)(((wm * 32 + (lane & 15)) * KPAD + (lane >> 4) * 4) * 4);

#pragma unroll
    for (int h = 0; h < 2; ++h) {
        const uint32_t aAddr = smem_u32(h ? As1 : As0) + aLane;
        float* C = h ? Ci : Cr;

        float c[2][2][4];
#pragma unroll
        for (int i = 0; i < 2; ++i)
#pragma unroll
            for (int j = 0; j < 2; ++j)
#pragma unroll
                for (int q = 0; q < 4; ++q) c[i][j][q] = 0.f;

#pragma unroll
        for (int ks = 0; ks < K / 8; ++ks) {
            const uint32_t kb = (uint32_t)(ks * 32);
            uint32_t a0[4], a1[4], b[4];
            ldsm_x4(a0[0], a0[1], a0[2], a0[3], aAddr + kb);
            ldsm_x4(a1[0], a1[1], a1[2], a1[3],
                    aAddr + (uint32_t)(16 * KPAD * 4) + kb);
            ldsm_x4(b[0], b[1], b[2], b[3], bAddr + kb);
            mma_tf32(c[0][0], a0, b);
            mma_tf32(c[0][1], a0, b + 2);
            mma_tf32(c[1][0], a1, b);
            mma_tf32(c[1][1], a1, b + 2);
        }

#pragma unroll
        for (int nt = 0; nt < 2; ++nt) {
            int col = wn * 16 + nt * 8 + (lane & 3) * 2;
            float bx = __ldg(bias + col);
            float by = __ldg(bias + col + 1);
#pragma unroll
            for (int mt = 0; mt < 2; ++mt) {
                int row0 = bm + wm * 32 + mt * 16 + (lane >> 2);
                float v0 = tf32r(c[mt][nt][0] + bx);
                float v1 = tf32r(c[mt][nt][1] + by);
                float v2 = tf32r(c[mt][nt][2] + bx);
                float v3 = tf32r(c[mt][nt][3] + by);
                if (row0 < M)
                    *reinterpret_cast<float2*>(C + (size_t)row0 * ldc + col) =
                        make_float2(v0, v1);
                if (row0 + 8 < M)
                    *reinterpret_cast<float2*>(C + (size_t)(row0 + 8) * ldc + col) =
                        make_float2(v2, v3);
            }
        }
    }
}

// -------------------- K-chunked MLP layer (merged real/imag) ----------------
// blockIdx.y selects stream (0=real inputs/outputs, 1=imag).
// MODE 0: A via cp.async (pre-rounded).  MODE 1: gather concat(E,H[row],H[col]).
// MODE 2: A cvt-staged (raw fp32, contiguous K=192) — replaces k_roundX.
template <int NOUT, int MODE>
__global__ __launch_bounds__(256, 2)
void k_layer(const float* __restrict__ A0, const float* __restrict__ A1,
             int M,
             const float* __restrict__ W,
             const float* __restrict__ bias,
             const float* __restrict__ alphaPtr,
             float* __restrict__ C0, float* __restrict__ C1, int roundOut,
             const float* __restrict__ GH0, const float* __restrict__ GH1)
{
    constexpr int K = 192, KC = 48, KCPAD = 52, NCH = K / KC;
    constexpr int NW = NOUT / 4;
    constexpr int NB = NW / 16;
    constexpr int CHF = (64 + NOUT) * KCPAD;
    extern __shared__ __align__(16) char smem[];
    float* buf0 = reinterpret_cast<float*>(smem);

    const int tid = threadIdx.x, lane = tid & 31, wid = tid >> 5;
    const int wm = wid >> 2, wn = wid & 3;
    const int bm = blockIdx.x * 64;
    const float* A  = blockIdx.y ? A1 : A0;
    float*       C  = blockIdx.y ? C1 : C0;
    const float* GH = blockIdx.y ? GH1 : GH0;

    auto stage = [&](int c, int b) {
        float* bufA = buf0 + b * CHF;
        float* bufB = bufA + 64 * KCPAD;
        const uint32_t A32 = smem_u32(bufA);
        const uint32_t B32 = smem_u32(bufB);
        if (MODE == 0) {
#pragma unroll
            for (int it = 0; it < 3; ++it) {
                int idx = tid + it * 256;
                int row = idx / 12, q = idx - row * 12;
                cp16(A32 + (uint32_t)((row * KCPAD + q * 4) * 4),
                     A + (size_t)(bm + row) * K + c * KC + q * 4);
            }
        } else if (MODE == 1) {
#pragma unroll
            for (int it = 0; it < 3; ++it) {
                int idx = tid + it * 256;
                int row = idx / 12, q = idx - row * 12;
                int e = bm + row;
                int gcol = c * KC + q * 4;
                int seg = gcol >> 6, off = gcol & 63;
                const float* src;
                if (seg == 0) {
                    src = A + (size_t)e * 64 + off;
                } else {
                    int n = (seg == 1) ? __ldg(&g_row[e]) : __ldg(&g_col[e]);
                    src = GH + (size_t)n * 64 + off;
                }
                float4 v = *reinterpret_cast<const float4*>(src);
                *reinterpret_cast<float4*>(bufA + row * KCPAD + q * 4) =
                    make_float4(tf32r(v.x), tf32r(v.y), tf32r(v.z), tf32r(v.w));
            }
        } else {
#pragma unroll
            for (int it = 0; it < 3; ++it) {
                int idx = tid + it * 256;
                int row = idx / 12, q = idx - row * 12;
                float4 v = *reinterpret_cast<const float4*>(
                    A + (size_t)(bm + row) * K + c * KC + q * 4);
                *reinterpret_cast<float4*>(bufA + row * KCPAD + q * 4) =
                    make_float4(tf32r(v.x), tf32r(v.y), tf32r(v.z), tf32r(v.w));
            }
        }
#pragma unroll
        for (int it = 0; it < NOUT * 12 / 256; ++it) {
            int idx = tid + it * 256;
            int n = idx / 12, q = idx - n * 12;
            cp16(B32 + (uint32_t)((n * KCPAD + q * 4) * 4),
                 W + (size_t)n * K + c * KC + q * 4);
        }
        asm volatile("cp.async.commit_group;");
    };

    const uint32_t aLaneOff =
        (uint32_t)(((wm * 32 + (lane & 15)) * KCPAD + (lane >> 4) * 4) * 4);
    const int nOff = (lane & 7) + ((lane >> 4) & 1) * 8;
    const int kcol = ((lane >> 3) & 1) * 4;
    uint32_t bLaneOff[NB];
#pragma unroll
    for (int j = 0; j < NB; ++j)
        bLaneOff[j] = (uint32_t)(((wn * NW + j * 16 + nOff) * KCPAD + kcol) * 4);

    float acc[2][NB * 2][4];
#pragma unroll
    for (int x = 0; x < 2; ++x)
#pragma unroll
        for (int y = 0; y < NB * 2; ++y)
#pragma unroll
            for (int q = 0; q < 4; ++q) acc[x][y][q] = 0.f;

    stage(0, 0);

#pragma unroll
    for (int c = 0; c < NCH; ++c) {
        if (c + 1 < NCH) {
            stage(c + 1, (c + 1) & 1);
            asm volatile("cp.async.wait_group 1;");
        } else {
            asm volatile("cp.async.wait_group 0;");
        }
        __syncthreads();

        float* bufA = buf0 + (c & 1) * CHF;
        const uint32_t B32 = smem_u32(bufA + 64 * KCPAD);
        const uint32_t aAddr = smem_u32(bufA) + aLaneOff;

#pragma unroll
        for (int ks = 0; ks < KC / 8; ++ks) {
            const uint32_t kb = (uint32_t)(ks * 32);
            uint32_t a0[4], a1[4];
            ldsm_x4(a0[0], a0[1], a0[2], a0[3], aAddr + kb);
            ldsm_x4(a1[0], a1[1], a1[2], a1[3],
                    aAddr + (uint32_t)(16 * KCPAD * 4) + kb);
#pragma unroll
            for (int j = 0; j < NB; ++j) {
                uint32_t b[4];
                ldsm_x4(b[0], b[1], b[2], b[3], B32 + bLaneOff[j] + kb);
                mma_tf32(acc[0][2 * j + 0], a0, b);
                mma_tf32(acc[0][2 * j + 1], a0, b + 2);
                mma_tf32(acc[1][2 * j + 0], a1, b);
                mma_tf32(acc[1][2 * j + 1], a1, b + 2);
            }
        }
        __syncthreads();
    }

    const bool  act = (alphaPtr != nullptr);
    const float al  = act ? __ldg(alphaPtr) : 1.0f;
#pragma unroll
    for (int nf = 0; nf < NB * 2; ++nf) {
        int col = wn * NW + nf * 8 + (lane & 3) * 2;
        float bx = __ldg(bias + col);
        float by = __ldg(bias + col + 1);
#pragma unroll
        for (int mf = 0; mf < 2; ++mf) {
            int row0 = bm + wm * 32 + mf * 16 + (lane >> 2);
            float v0 = acc[mf][nf][0] + bx;
            float v1 = acc[mf][nf][1] + by;
            float v2 = acc[mf][nf][2] + bx;
            float v3 = acc[mf][nf][3] + by;
            if (act) {
                v0 = (v0 >= 0.f) ? v0 : al * v0;
                v1 = (v1 >= 0.f) ? v1 : al * v1;
                v2 = (v2 >= 0.f) ? v2 : al * v2;
                v3 = (v3 >= 0.f) ? v3 : al * v3;
            }
            if (roundOut) {
                v0 = tf32r(v0); v1 = tf32r(v1);
                v2 = tf32r(v2); v3 = tf32r(v3);
            }
            if (row0 < M)
                *reinterpret_cast<float2*>(C + (size_t)row0 * NOUT + col) =
                    make_float2(v0, v1);
            if (row0 + 8 < M)
                *reinterpret_cast<float2*>(C + (size_t)(row0 + 8) * NOUT + col) =
                    make_float2(v2, v3);
        }
    }
}

// -------------------- node aggregation (segment-sum via atomics) ------------
__global__ void k_scatter() {
    int t = blockIdx.x * blockDim.x + threadIdx.x;
    if (t >= N_EDGES * IN_F) return;
    int e = t >> 6;
    int f = t & 63;
    int r = g_row[e];
    int c = g_col[e];

    float vnr = g_Xr[(size_t)c * HDIM + f];
    float vni = g_Xi[(size_t)c * HDIM + f];
    float ver = g_Er[(size_t)e * 64 + f];
    float vei = g_Ei[(size_t)e * 64 + f];

    atomicAdd(&g_Xr[(size_t)r * HDIM + 64  + f], vnr);
    atomicAdd(&g_Xr[(size_t)r * HDIM + 128 + f], ver);
    atomicAdd(&g_Xi[(size_t)r * HDIM + 64  + f], vni);
    atomicAdd(&g_Xi[(size_t)r * HDIM + 128 + f], vei);
}

// ---------------------------------------------------------------------------
static float* symaddr(const void* sym) {
    void* p = nullptr;
    cudaGetSymbolAddress(&p, sym);
    return (float*)p;
}

extern "C" void kernel_launch(void* const* d_in, const int* in_sizes, int n_in,
                              void* d_out, int out_size)
{
    const float* node_real = (const float*)d_in[0];
    const float* node_imag = (const float*)d_in[1];
    const float* edge_real = (const float*)d_in[2];
    const float* edge_imag = (const float*)d_in[3];
    const void*  edge_idx  = d_in[4];
    const float* Wn        = (const float*)d_in[5];
    const float* bn_       = (const float*)d_in[6];
    const float* We        = (const float*)d_in[7];
    const float* be_       = (const float*)d_in[8];
    const float* node_W    = (const float*)d_in[9];
    const float* node_b    = (const float*)d_in[10];
    const float* node_al   = (const float*)d_in[11];
    const float* node_oW   = (const float*)d_in[12];
    const float* node_ob   = (const float*)d_in[13];
    const float* edge_W    = (const float*)d_in[14];
    const float* edge_b    = (const float*)d_in[15];
    const float* edge_al   = (const float*)d_in[16];
    const float* edge_oW   = (const float*)d_in[17];
    const float* edge_ob   = (const float*)d_in[18];

    float* out  = (float*)d_out;
    float* hr   = out;
    float* hi   = out + (size_t)N_NODES * OUT_F;
    float* outr = out + 2 * (size_t)N_NODES * OUT_F;
    float* outi = outr + (size_t)N_EDGES * OUT_F;

    float* Xr  = symaddr(g_Xr);
    float* Xi  = symaddr(g_Xi);
    float* Xt  = symaddr(g_Xt);
    float* Xu  = symaddr(g_Xu);
    float* Xt2 = symaddr(g_Xt2);
    float* Xu2 = symaddr(g_Xu2);
    float* Er  = symaddr(g_Er);
    float* Ei  = symaddr(g_Ei);
    float* Yt  = symaddr(g_Yt);
    float* Yu  = symaddr(g_Yu);
    float* Zt  = symaddr(g_Zt);
    float* Zu  = symaddr(g_Zu);
    float* Wt  = symaddr(g_Wt);

    const int SMEM_PROJ2 = (128 + 64) * 68 * 4;         // 52.2 KB -> 4 CTA/SM
    const int SMEM_L192  = 2 * (64 + 192) * 52 * 4;     // 106.5 KB -> 2 CTA/SM
    const int SMEM_L64   = 2 * (64 + 64) * 52 * 4;      // 53.2 KB
    cudaFuncSetAttribute(k_proj2, cudaFuncAttributeMaxDynamicSharedMemorySize, SMEM_PROJ2);
    cudaFuncSetAttribute(k_layer<192, 0>, cudaFuncAttributeMaxDynamicSharedMemorySize, SMEM_L192);
    cudaFuncSetAttribute(k_layer<192, 1>, cudaFuncAttributeMaxDynamicSharedMemorySize, SMEM_L192);
    cudaFuncSetAttribute(k_layer<192, 2>, cudaFuncAttributeMaxDynamicSharedMemorySize, SMEM_L192);
    cudaFuncSetAttribute(k_layer<64, 0>,  cudaFuncAttributeMaxDynamicSharedMemorySize, SMEM_L64);

    const int TPB = 256;
    const int gN  = (N_NODES + 63) / 64;   // 391
    const int gE  = N_EDGES / 64;          // 3125
    const int HH  = HDIM * HDIM;

    // 1-2. edge index conversion
    k_detect<<<1, 32>>>((const unsigned int*)edge_idx);
    k_convert<<<(N_EDGES + TPB - 1) / TPB, TPB>>>(edge_idx);

    // 3. weight prep (tf32 round)
    k_prepW<<<dim3(432, 6), TPB>>>(Wn, We, node_W, node_oW, edge_W, edge_oW);

    // 4. zero node agg region (cols 64:192 only)
    k_zeroX<<<(N_NODES * 128 + TPB - 1) / TPB, TPB>>>();

    // 5-6. merged projections (real+imag per CTA)
    k_proj2<<<gE, TPB, SMEM_PROJ2>>>(edge_real, edge_imag, N_EDGES,
                                     Wt + OFF_WE, be_, Er, Ei, OUT_F);
    k_proj2<<<gN, TPB, SMEM_PROJ2>>>(node_real, node_imag, N_NODES,
                                     Wt + OFF_WN, bn_, Xr, Xi, HDIM);

    // 7. node aggregation (X cols 64:192 accumulate raw fp32)
    k_scatter<<<(N_EDGES * IN_F + TPB - 1) / TPB, TPB>>>();

    // 8-11. node MLP, real+imag merged per launch
    // layer1 cvt-stages raw Xr/Xi (tf32 round at load == old k_roundX path)
    k_layer<192, 2><<<dim3(gN, 2), TPB, SMEM_L192>>>(Xr, Xi, N_NODES,
        Wt + OFF_NW,        node_b,          node_al,     Xt, Xt2, 1, nullptr, nullptr);
    k_layer<192, 0><<<dim3(gN, 2), TPB, SMEM_L192>>>(Xt, Xt2, N_NODES,
        Wt + OFF_NW + HH,   node_b + HDIM,   node_al + 1, Xu, Xu2, 1, nullptr, nullptr);
    k_layer<192, 0><<<dim3(gN, 2), TPB, SMEM_L192>>>(Xu, Xu2, N_NODES,
        Wt + OFF_NW + 2*HH, node_b + 2*HDIM, node_al + 2, Xt, Xt2, 1, nullptr, nullptr);
    k_layer<64, 0><<<dim3(gN, 2), TPB, SMEM_L64>>>(Xt, Xt2, N_NODES,
        Wt + OFF_NOW, node_ob, nullptr, hr, hi, 0, nullptr, nullptr);

    // 12-15. edge MLP, real+imag merged per launch (layer1 gathers hr/hi)
    k_layer<192, 1><<<dim3(gE, 2), TPB, SMEM_L192>>>(Er, Ei, N_EDGES,
        Wt + OFF_EW,        edge_b,          edge_al,     Yt, Zt, 1, hr, hi);
    k_layer<192, 0><<<dim3(gE, 2), TPB, SMEM_L192>>>(Yt, Zt, N_EDGES,
        Wt + OFF_EW + HH,   edge_b + HDIM,   edge_al + 1, Yu, Zu, 1, nullptr, nullptr);
    k_layer<192, 0><<<dim3(gE, 2), TPB, SMEM_L192>>>(Yu, Zu, N_EDGES,
        Wt + OFF_EW + 2*HH, edge_b + 2*HDIM, edge_al + 2, Yt, Zt, 1, nullptr, nullptr);
    k_layer<64, 0><<<dim3(gE, 2), TPB, SMEM_L64>>>(Yt, Zt, N_EDGES,
        Wt + OFF_EOW, edge_ob, nullptr, outr, outi, 0, nullptr, nullptr);
}